// round 3
// baseline (speedup 1.0000x reference)
#include <cuda_runtime.h>
#include <stdint.h>
#include <math_constants.h>

// ---------------- problem constants ----------------
constexpr int BROWS = 16384;   // batch
constexpr int DIN   = 2048;    // input dim
constexpr int LAT   = 512;     // latent
constexpr int KE    = 256;     // 16x16 embeddings
constexpr int SOMW  = 16;

// output offsets (float32 elements, concatenated in reference return order)
constexpr size_t OFF_XE   = 0;
constexpr size_t OFF_XQ   = OFF_XE + (size_t)BROWS * DIN;        // 33554432
constexpr size_t OFF_ZE   = OFF_XQ + (size_t)BROWS * DIN;        // 67108864
constexpr size_t OFF_ZQ   = OFF_ZE + (size_t)BROWS * LAT;        // 75497472
constexpr size_t OFF_NB   = OFF_ZQ + (size_t)BROWS * LAT;        // 83886080
constexpr size_t OFF_K    = OFF_NB + (size_t)BROWS * 5 * LAT;    // 125829120
constexpr size_t OFF_DIST = OFF_K  + (size_t)BROWS;              // 125845504

// ---------------- device scratch (no allocations allowed) ----------------
__device__ float g_zsq[BROWS];
__device__ float g_esq[KE];
__device__ float g_U[(size_t)KE * DIN];   // emb_flat @ dec_q_w + dec_q_b
__device__ int   g_k[BROWS];
__device__ int   g_cand[BROWS * 4];       // top-4 fp32-argmin candidates per row

// =====================================================================
// Generic 128x128x8 register-blocked SGEMM: C = A[M,K] @ W[K,N] + bias
// =====================================================================
__global__ __launch_bounds__(256) void gemm_bias_kernel(
    const float* __restrict__ A, const float* __restrict__ W,
    const float* __restrict__ bias, float* __restrict__ C,
    int M, int N, int K)
{
    constexpr int BM = 128, BN = 128, BK = 8;
    __shared__ float As[BK][BM];
    __shared__ float Ws[BK][BN];

    const int tid = threadIdx.x;
    const int m0 = blockIdx.y * BM;
    const int n0 = blockIdx.x * BN;
    const int ty = tid >> 4;
    const int tx = tid & 15;

    const int arow = tid >> 1;
    const int acol = (tid & 1) * 4;
    const int wrow = tid >> 5;
    const int wcol = (tid & 31) * 4;

    float acc[8][8];
#pragma unroll
    for (int i = 0; i < 8; i++)
#pragma unroll
        for (int j = 0; j < 8; j++) acc[i][j] = 0.f;

    const float* aptr = A + (size_t)(m0 + arow) * K + acol;
    const float* wptr = W + (size_t)wrow * N + n0 + wcol;

    for (int k0 = 0; k0 < K; k0 += BK) {
        float4 av = *(const float4*)(aptr + k0);
        float4 wv = *(const float4*)(wptr + (size_t)k0 * N);
        As[acol + 0][arow] = av.x;
        As[acol + 1][arow] = av.y;
        As[acol + 2][arow] = av.z;
        As[acol + 3][arow] = av.w;
        *(float4*)&Ws[wrow][wcol] = wv;
        __syncthreads();
#pragma unroll
        for (int kk = 0; kk < BK; kk++) {
            float rm[8], rn[8];
            *(float4*)&rm[0] = *(const float4*)&As[kk][ty * 8];
            *(float4*)&rm[4] = *(const float4*)&As[kk][ty * 8 + 4];
            *(float4*)&rn[0] = *(const float4*)&Ws[kk][tx * 8];
            *(float4*)&rn[4] = *(const float4*)&Ws[kk][tx * 8 + 4];
#pragma unroll
            for (int i = 0; i < 8; i++)
#pragma unroll
                for (int j = 0; j < 8; j++)
                    acc[i][j] += rm[i] * rn[j];
        }
        __syncthreads();
    }

    float bj[8];
#pragma unroll
    for (int j = 0; j < 8; j++) bj[j] = bias[n0 + tx * 8 + j];

#pragma unroll
    for (int i = 0; i < 8; i++) {
        float* c = C + (size_t)(m0 + ty * 8 + i) * N + n0 + tx * 8;
        float4 v0, v1;
        v0.x = acc[i][0] + bj[0]; v0.y = acc[i][1] + bj[1];
        v0.z = acc[i][2] + bj[2]; v0.w = acc[i][3] + bj[3];
        v1.x = acc[i][4] + bj[4]; v1.y = acc[i][5] + bj[5];
        v1.z = acc[i][6] + bj[6]; v1.w = acc[i][7] + bj[7];
        *(float4*)c       = v0;
        *(float4*)(c + 4) = v1;
    }
}

// =====================================================================
// dist[b,e] = (g_zsq[b] - 2 * t) + g_esq[e], fp32 (output + candidate sel)
// =====================================================================
__global__ __launch_bounds__(256) void dist_kernel(
    const float* __restrict__ Z, const float* __restrict__ E,
    float* __restrict__ D)
{
    constexpr int BM = 128, BN = 128, BK = 8;
    __shared__ float Zs[BK][BM];
    __shared__ float Es[BK][BN];

    const int tid = threadIdx.x;
    const int m0 = blockIdx.y * BM;
    const int n0 = blockIdx.x * BN;
    const int ty = tid >> 4;
    const int tx = tid & 15;

    const int arow = tid >> 1;
    const int acol = (tid & 1) * 4;

    float acc[8][8];
#pragma unroll
    for (int i = 0; i < 8; i++)
#pragma unroll
        for (int j = 0; j < 8; j++) acc[i][j] = 0.f;

    const float* zptr = Z + (size_t)(m0 + arow) * LAT + acol;
    const float* eptr = E + (size_t)(n0 + arow) * LAT + acol;

    for (int k0 = 0; k0 < LAT; k0 += BK) {
        float4 zv = *(const float4*)(zptr + k0);
        float4 ev = *(const float4*)(eptr + k0);
        Zs[acol + 0][arow] = zv.x;
        Zs[acol + 1][arow] = zv.y;
        Zs[acol + 2][arow] = zv.z;
        Zs[acol + 3][arow] = zv.w;
        Es[acol + 0][arow] = ev.x;
        Es[acol + 1][arow] = ev.y;
        Es[acol + 2][arow] = ev.z;
        Es[acol + 3][arow] = ev.w;
        __syncthreads();
#pragma unroll
        for (int kk = 0; kk < BK; kk++) {
            float rm[8], rn[8];
            *(float4*)&rm[0] = *(const float4*)&Zs[kk][ty * 8];
            *(float4*)&rm[4] = *(const float4*)&Zs[kk][ty * 8 + 4];
            *(float4*)&rn[0] = *(const float4*)&Es[kk][tx * 8];
            *(float4*)&rn[4] = *(const float4*)&Es[kk][tx * 8 + 4];
#pragma unroll
            for (int i = 0; i < 8; i++)
#pragma unroll
                for (int j = 0; j < 8; j++)
                    acc[i][j] += rm[i] * rn[j];
        }
        __syncthreads();
    }

#pragma unroll
    for (int i = 0; i < 8; i++) {
        int m = m0 + ty * 8 + i;
        float zs = g_zsq[m];
        float* d = D + (size_t)m * KE + n0 + tx * 8;
#pragma unroll
        for (int j = 0; j < 8; j++) {
            float t = acc[i][j];
            float a = zs - 2.f * t;          // mirrors reference op order
            d[j] = a + g_esq[n0 + tx * 8 + j];
        }
    }
}

// ---------------- per-row sum of squares, fp64 accumulate -> fp32 ----------------
__global__ void rowsq_kernel(const float* __restrict__ Z, float* __restrict__ out,
                             int rows, int cols)
{
    int row = blockIdx.x * (blockDim.x >> 5) + (threadIdx.x >> 5);
    int lane = threadIdx.x & 31;
    if (row >= rows) return;
    const float* z = Z + (size_t)row * cols;
    double s = 0.0;
    for (int j = lane; j < cols; j += 32) {
        double v = (double)z[j];
        s += v * v;
    }
#pragma unroll
    for (int o = 16; o > 0; o >>= 1) s += __shfl_xor_sync(0xffffffffu, s, o);
    if (lane == 0) out[row] = (float)s;
}

// ---------------- top-4 fp32 argmin candidates per row ----------------
__global__ __launch_bounds__(256) void argmin_top4_kernel(
    const float* __restrict__ dist)
{
    const int row = blockIdx.x;
    const int t = threadIdx.x;
    __shared__ float sv[256];
    __shared__ int   si[256];

    const float myv = dist[(size_t)row * KE + t];
    int chosen0 = -1, chosen1 = -1, chosen2 = -1;

#pragma unroll
    for (int r = 0; r < 4; r++) {
        float v = myv;
        if (t == chosen0 || t == chosen1 || t == chosen2) v = CUDART_INF_F;
        sv[t] = v;
        si[t] = t;
        __syncthreads();
#pragma unroll
        for (int s = 128; s > 0; s >>= 1) {
            if (t < s) {
                float v2 = sv[t + s]; int i2 = si[t + s];
                if (v2 < sv[t] || (v2 == sv[t] && i2 < si[t])) { sv[t] = v2; si[t] = i2; }
            }
            __syncthreads();
        }
        int w = si[0];
        if (t == 0) g_cand[row * 4 + r] = w;
        if (r == 0) chosen0 = w;
        else if (r == 1) chosen1 = w;
        else if (r == 2) chosen2 = w;
        __syncthreads();
    }
}

// ---------------- refine: exact fp64 dot for top-4, reference-rounded dist ----------------
__global__ __launch_bounds__(128) void refine_kernel(
    const float* __restrict__ ZE, const float* __restrict__ emb,
    float* __restrict__ out)
{
    const int row = blockIdx.x;
    const int w = threadIdx.x >> 5;     // warp -> candidate slot
    const int lane = threadIdx.x & 31;

    __shared__ float cv[4];
    __shared__ int   ci[4];

    const int cand = g_cand[row * 4 + w];
    const float* z = ZE + (size_t)row * LAT;
    const float* e = emb + (size_t)cand * LAT;

    double s = 0.0;
    for (int j = lane; j < LAT; j += 32)
        s += (double)z[j] * (double)e[j];
#pragma unroll
    for (int o = 16; o > 0; o >>= 1) s += __shfl_xor_sync(0xffffffffu, s, o);

    if (lane == 0) {
        float t = (float)s;                      // true-rounded dot
        float a = g_zsq[row] - 2.f * t;          // reference fp32 op sequence
        float d = a + g_esq[cand];
        cv[w] = d;
        ci[w] = cand;
    }
    __syncthreads();

    if (threadIdx.x == 0) {
        float bv = cv[0]; int bi = ci[0];
#pragma unroll
        for (int r = 1; r < 4; r++) {
            float v = cv[r]; int i = ci[r];
            if (v < bv || (v == bv && i < bi)) { bv = v; bi = i; }
        }
        g_k[row] = bi;
        out[OFF_K + row] = (float)bi;
    }
}

// ---------------- z_q / neighbor gathers from refined k ----------------
__global__ __launch_bounds__(256) void gather_kernel(
    const float* __restrict__ emb, float* __restrict__ out)
{
    const int row = blockIdx.x;
    const int t = threadIdx.x;
    const int k = g_k[row];

    const int k1 = k / SOMW;
    const int k2 = k % SOMW;
    const float* src0 = emb + (size_t)k * LAT;
    const float* src1 = (k1 < SOMW - 1) ? emb + (size_t)(k + SOMW) * LAT : nullptr; // up
    const float* src2 = (k1 > 0)        ? emb + (size_t)(k - SOMW) * LAT : nullptr; // down
    const float* src4 = (k2 > 0)        ? emb + (size_t)(k - 1) * LAT    : nullptr; // left

    float* zq = out + OFF_ZQ + (size_t)row * LAT;
    float* nb = out + OFF_NB + (size_t)row * 5 * LAT;
    for (int i = t; i < LAT; i += 256) {
        float v0 = src0[i];
        zq[i] = v0;
        nb[i] = v0;
        nb[LAT + i]     = src1 ? src1[i] : 0.f;
        nb[2 * LAT + i] = src2 ? src2[i] : 0.f;
        nb[3 * LAT + i] = 0.f;                   // right (faithful bug: always 0)
        nb[4 * LAT + i] = src4 ? src4[i] : 0.f;
    }
}

// ---------------- x_q gather: x_q[b] = g_U[k[b]] ----------------
__global__ __launch_bounds__(256) void xq_gather_kernel(float* __restrict__ out)
{
    const int row = blockIdx.x;
    const int k = g_k[row];
    const float4* src = (const float4*)(g_U + (size_t)k * DIN);
    float4* dst = (float4*)(out + OFF_XQ + (size_t)row * DIN);
    for (int i = threadIdx.x; i < DIN / 4; i += 256)
        dst[i] = src[i];
}

// =====================================================================
extern "C" void kernel_launch(void* const* d_in, const int* in_sizes, int n_in,
                              void* d_out, int out_size)
{
    const float* x       = (const float*)d_in[0];
    const float* enc_w   = (const float*)d_in[1];
    const float* enc_b   = (const float*)d_in[2];
    const float* dec_q_w = (const float*)d_in[3];
    const float* dec_q_b = (const float*)d_in[4];
    const float* dec_e_w = (const float*)d_in[5];
    const float* dec_e_b = (const float*)d_in[6];
    const float* emb     = (const float*)d_in[7];
    float* out = (float*)d_out;

    float* zsq_p; cudaGetSymbolAddress((void**)&zsq_p, g_zsq);
    float* esq_p; cudaGetSymbolAddress((void**)&esq_p, g_esq);
    float* U_p;   cudaGetSymbolAddress((void**)&U_p,   g_U);

    dim3 blk(256);

    // 1) z_e = x @ enc_w + enc_b        [16384,2048]x[2048,512]
    gemm_bias_kernel<<<dim3(LAT / 128, BROWS / 128), blk>>>(
        x, enc_w, enc_b, out + OFF_ZE, BROWS, LAT, DIN);

    // 2) U = emb_flat @ dec_q_w + dec_q_b   [256,512]x[512,2048]
    gemm_bias_kernel<<<dim3(DIN / 128, KE / 128), blk>>>(
        emb, dec_q_w, dec_q_b, U_p, KE, DIN, LAT);

    // 3) row sums of squares (fp64 accumulate -> fp32)
    rowsq_kernel<<<BROWS / 8, 256>>>(out + OFF_ZE, zsq_p, BROWS, LAT);
    rowsq_kernel<<<KE / 8, 256>>>(emb, esq_p, KE, LAT);

    // 4) z_dist_flat (fp32, fast path; output + candidate selection)
    dist_kernel<<<dim3(KE / 128, BROWS / 128), blk>>>(
        out + OFF_ZE, emb, out + OFF_DIST);

    // 5) top-4 fp32 candidates, then exact fp64 refine -> k
    argmin_top4_kernel<<<BROWS, 256>>>(out + OFF_DIST);
    refine_kernel<<<BROWS, 128>>>(out + OFF_ZE, emb, out);

    // 6) gathers from refined k
    gather_kernel<<<BROWS, 256>>>(emb, out);
    xq_gather_kernel<<<BROWS, 256>>>(out);

    // 7) x_e = z_e @ dec_e_w + dec_e_b   [16384,512]x[512,2048]
    gemm_bias_kernel<<<dim3(DIN / 128, BROWS / 128), blk>>>(
        out + OFF_ZE, dec_e_w, dec_e_b, out + OFF_XE, BROWS, DIN, LAT);
}

// round 4
// speedup vs baseline: 1.0877x; 1.0877x over previous
#include <cuda_runtime.h>
#include <stdint.h>
#include <math_constants.h>

// ---------------- problem constants ----------------
constexpr int BROWS = 16384;   // batch
constexpr int DIN   = 2048;    // input dim
constexpr int LAT   = 512;     // latent
constexpr int KE    = 256;     // 16x16 embeddings
constexpr int SOMW  = 16;

// output offsets (float32 elements, concatenated in reference return order)
constexpr size_t OFF_XE   = 0;
constexpr size_t OFF_XQ   = OFF_XE + (size_t)BROWS * DIN;
constexpr size_t OFF_ZE   = OFF_XQ + (size_t)BROWS * DIN;
constexpr size_t OFF_ZQ   = OFF_ZE + (size_t)BROWS * LAT;
constexpr size_t OFF_NB   = OFF_ZQ + (size_t)BROWS * LAT;
constexpr size_t OFF_K    = OFF_NB + (size_t)BROWS * 5 * LAT;
constexpr size_t OFF_DIST = OFF_K  + (size_t)BROWS;

// ---------------- device scratch (no allocations allowed) ----------------
__device__ float g_zsq[BROWS];
__device__ float g_esq[KE];
__device__ float g_U[(size_t)KE * DIN];
__device__ int   g_k[BROWS];
__device__ int   g_cand[BROWS * 4];

// ---------------- tf32 split helpers ----------------
__device__ __forceinline__ float ftr(float x) {
    return __uint_as_float(__float_as_uint(x) & 0xFFFFE000u);
}

__device__ __forceinline__ void mma8(float* c, const uint32_t* a, const uint32_t* b) {
    asm volatile(
        "mma.sync.aligned.m16n8k8.row.col.f32.tf32.tf32.f32 "
        "{%0,%1,%2,%3}, {%4,%5,%6,%7}, {%8,%9}, {%0,%1,%2,%3};\n"
        : "+f"(c[0]), "+f"(c[1]), "+f"(c[2]), "+f"(c[3])
        : "r"(a[0]), "r"(a[1]), "r"(a[2]), "r"(a[3]), "r"(b[0]), "r"(b[1]));
}

constexpr int BM = 128, BN = 128, BK = 16, SB = 20;

// =====================================================================
// 3-pass tf32 tensor GEMM (fp32-emulation accuracy)
// MODE 0: C = A[M,K] @ B[K,N] + bias[N]
// MODE 1: C = (g_zsq[m] - 2*(A[M,K] @ B[N,K]^T)) + g_esq[n]   (dist)
// =====================================================================
template <int MODE>
__global__ __launch_bounds__(256) void gemm3t(
    const float* __restrict__ A, const float* __restrict__ B,
    const float* __restrict__ bias, float* __restrict__ C,
    int M, int N, int K)
{
    __shared__ float Ah[BM * SB], Al[BM * SB];
    __shared__ float Bh[BN * SB], Bl[BN * SB];

    const int tid = threadIdx.x, lane = tid & 31, warp = tid >> 5;
    const int wm = warp >> 1;        // 0..3 -> 32-row slice
    const int wn = warp & 1;         // 0..1 -> 64-col slice
    const int m0 = blockIdx.y * BM, n0 = blockIdx.x * BN;
    const int rq = lane >> 2, cq = lane & 3;

    // loader indices
    const int arow = tid >> 1, acol = (tid & 1) * 8;     // A (and B in MODE1)
    const int bn = tid & 127, bk0 = (tid >> 7) * 8;      // B in MODE0 (transpose)

    float acc[2][8][4];
#pragma unroll
    for (int mt = 0; mt < 2; mt++)
#pragma unroll
        for (int nt = 0; nt < 8; nt++)
#pragma unroll
            for (int r = 0; r < 4; r++) acc[mt][nt][r] = 0.f;

    float4 pa0, pa1, pb0, pb1;
    float pbv[8];

    const int nch = K / BK;

    // initial prefetch (chunk 0)
    {
        const float* ap = A + (size_t)(m0 + arow) * K + acol;
        pa0 = *(const float4*)ap;
        pa1 = *(const float4*)(ap + 4);
        if (MODE == 0) {
#pragma unroll
            for (int j = 0; j < 8; j++)
                pbv[j] = B[(size_t)(bk0 + j) * N + n0 + bn];
        } else {
            const float* bp = B + (size_t)(n0 + arow) * K + acol;
            pb0 = *(const float4*)bp;
            pb1 = *(const float4*)(bp + 4);
        }
    }

    for (int ch = 0; ch < nch; ch++) {
        // ---- stage prefetched regs into smem as hi/lo ----
        {
            float4 h, l;
            h.x = ftr(pa0.x); h.y = ftr(pa0.y); h.z = ftr(pa0.z); h.w = ftr(pa0.w);
            l.x = pa0.x - h.x; l.y = pa0.y - h.y; l.z = pa0.z - h.z; l.w = pa0.w - h.w;
            *(float4*)&Ah[arow * SB + acol] = h;
            *(float4*)&Al[arow * SB + acol] = l;
            h.x = ftr(pa1.x); h.y = ftr(pa1.y); h.z = ftr(pa1.z); h.w = ftr(pa1.w);
            l.x = pa1.x - h.x; l.y = pa1.y - h.y; l.z = pa1.z - h.z; l.w = pa1.w - h.w;
            *(float4*)&Ah[arow * SB + acol + 4] = h;
            *(float4*)&Al[arow * SB + acol + 4] = l;

            if (MODE == 0) {
#pragma unroll
                for (int j = 0; j < 8; j++) {
                    float hh = ftr(pbv[j]);
                    Bh[bn * SB + bk0 + j] = hh;
                    Bl[bn * SB + bk0 + j] = pbv[j] - hh;
                }
            } else {
                h.x = ftr(pb0.x); h.y = ftr(pb0.y); h.z = ftr(pb0.z); h.w = ftr(pb0.w);
                l.x = pb0.x - h.x; l.y = pb0.y - h.y; l.z = pb0.z - h.z; l.w = pb0.w - h.w;
                *(float4*)&Bh[arow * SB + acol] = h;
                *(float4*)&Bl[arow * SB + acol] = l;
                h.x = ftr(pb1.x); h.y = ftr(pb1.y); h.z = ftr(pb1.z); h.w = ftr(pb1.w);
                l.x = pb1.x - h.x; l.y = pb1.y - h.y; l.z = pb1.z - h.z; l.w = pb1.w - h.w;
                *(float4*)&Bh[arow * SB + acol + 4] = h;
                *(float4*)&Bl[arow * SB + acol + 4] = l;
            }
        }
        __syncthreads();

        // ---- prefetch next chunk (overlaps compute) ----
        if (ch + 1 < nch) {
            const int k0 = (ch + 1) * BK;
            const float* ap = A + (size_t)(m0 + arow) * K + k0 + acol;
            pa0 = *(const float4*)ap;
            pa1 = *(const float4*)(ap + 4);
            if (MODE == 0) {
#pragma unroll
                for (int j = 0; j < 8; j++)
                    pbv[j] = B[(size_t)(k0 + bk0 + j) * N + n0 + bn];
            } else {
                const float* bp = B + (size_t)(n0 + arow) * K + k0 + acol;
                pb0 = *(const float4*)bp;
                pb1 = *(const float4*)(bp + 4);
            }
        }

        // ---- compute: 2 x k8 steps, 3 mma passes each ----
#pragma unroll
        for (int ks = 0; ks < BK; ks += 8) {
            uint32_t ah[2][4], al[2][4], bh[8][2], bl[8][2];
#pragma unroll
            for (int mt = 0; mt < 2; mt++) {
                const int i0 = (wm * 32 + mt * 16 + rq) * SB + ks + cq;
                ah[mt][0] = __float_as_uint(Ah[i0]);
                ah[mt][1] = __float_as_uint(Ah[i0 + 8 * SB]);
                ah[mt][2] = __float_as_uint(Ah[i0 + 4]);
                ah[mt][3] = __float_as_uint(Ah[i0 + 8 * SB + 4]);
                al[mt][0] = __float_as_uint(Al[i0]);
                al[mt][1] = __float_as_uint(Al[i0 + 8 * SB]);
                al[mt][2] = __float_as_uint(Al[i0 + 4]);
                al[mt][3] = __float_as_uint(Al[i0 + 8 * SB + 4]);
            }
#pragma unroll
            for (int nt = 0; nt < 8; nt++) {
                const int i0 = (wn * 64 + nt * 8 + rq) * SB + ks + cq;
                bh[nt][0] = __float_as_uint(Bh[i0]);
                bh[nt][1] = __float_as_uint(Bh[i0 + 4]);
                bl[nt][0] = __float_as_uint(Bl[i0]);
                bl[nt][1] = __float_as_uint(Bl[i0 + 4]);
            }
#pragma unroll
            for (int mt = 0; mt < 2; mt++)
#pragma unroll
                for (int nt = 0; nt < 8; nt++) {
                    mma8(acc[mt][nt], ah[mt], bl[nt]);
                    mma8(acc[mt][nt], al[mt], bh[nt]);
                    mma8(acc[mt][nt], ah[mt], bh[nt]);
                }
        }
        __syncthreads();
    }

    // ---- epilogue ----
#pragma unroll
    for (int mt = 0; mt < 2; mt++) {
        const int row = m0 + wm * 32 + mt * 16 + rq;
#pragma unroll
        for (int nt = 0; nt < 8; nt++) {
            const int col = n0 + wn * 64 + nt * 8 + 2 * cq;
            float* c = acc[mt][nt];
            if (MODE == 0) {
                const float b0 = bias[col], b1 = bias[col + 1];
                float2 v0 = make_float2(c[0] + b0, c[1] + b1);
                float2 v1 = make_float2(c[2] + b0, c[3] + b1);
                *(float2*)&C[(size_t)row * N + col] = v0;
                *(float2*)&C[(size_t)(row + 8) * N + col] = v1;
            } else {
                const float zs0 = g_zsq[row], zs1 = g_zsq[row + 8];
                const float e0 = g_esq[col], e1 = g_esq[col + 1];
                float2 v0 = make_float2((zs0 - 2.f * c[0]) + e0, (zs0 - 2.f * c[1]) + e1);
                float2 v1 = make_float2((zs1 - 2.f * c[2]) + e0, (zs1 - 2.f * c[3]) + e1);
                *(float2*)&C[(size_t)row * N + col] = v0;
                *(float2*)&C[(size_t)(row + 8) * N + col] = v1;
            }
        }
    }
}

// ---------------- per-row sum of squares, fp64 accumulate -> fp32 ----------------
__global__ void rowsq_kernel(const float* __restrict__ Z, float* __restrict__ out,
                             int rows, int cols)
{
    int row = blockIdx.x * (blockDim.x >> 5) + (threadIdx.x >> 5);
    int lane = threadIdx.x & 31;
    if (row >= rows) return;
    const float* z = Z + (size_t)row * cols;
    double s = 0.0;
    for (int j = lane; j < cols; j += 32) {
        double v = (double)z[j];
        s += v * v;
    }
#pragma unroll
    for (int o = 16; o > 0; o >>= 1) s += __shfl_xor_sync(0xffffffffu, s, o);
    if (lane == 0) out[row] = (float)s;
}

// ---------------- top-4 fp32 argmin candidates per row ----------------
__global__ __launch_bounds__(256) void argmin_top4_kernel(
    const float* __restrict__ dist)
{
    const int row = blockIdx.x;
    const int t = threadIdx.x;
    __shared__ float sv[256];
    __shared__ int   si[256];

    const float myv = dist[(size_t)row * KE + t];
    int chosen0 = -1, chosen1 = -1, chosen2 = -1;

#pragma unroll
    for (int r = 0; r < 4; r++) {
        float v = myv;
        if (t == chosen0 || t == chosen1 || t == chosen2) v = CUDART_INF_F;
        sv[t] = v;
        si[t] = t;
        __syncthreads();
#pragma unroll
        for (int s = 128; s > 0; s >>= 1) {
            if (t < s) {
                float v2 = sv[t + s]; int i2 = si[t + s];
                if (v2 < sv[t] || (v2 == sv[t] && i2 < si[t])) { sv[t] = v2; si[t] = i2; }
            }
            __syncthreads();
        }
        int w = si[0];
        if (t == 0) g_cand[row * 4 + r] = w;
        if (r == 0) chosen0 = w;
        else if (r == 1) chosen1 = w;
        else if (r == 2) chosen2 = w;
        __syncthreads();
    }
}

// ---------------- refine: exact fp64 dot for top-4, reference-rounded dist ----------------
__global__ __launch_bounds__(128) void refine_kernel(
    const float* __restrict__ ZE, const float* __restrict__ emb,
    float* __restrict__ out)
{
    const int row = blockIdx.x;
    const int w = threadIdx.x >> 5;
    const int lane = threadIdx.x & 31;

    __shared__ float cv[4];
    __shared__ int   ci[4];

    const int cand = g_cand[row * 4 + w];
    const float* z = ZE + (size_t)row * LAT;
    const float* e = emb + (size_t)cand * LAT;

    double s = 0.0;
    for (int j = lane; j < LAT; j += 32)
        s += (double)z[j] * (double)e[j];
#pragma unroll
    for (int o = 16; o > 0; o >>= 1) s += __shfl_xor_sync(0xffffffffu, s, o);

    if (lane == 0) {
        float t = (float)s;
        float a = g_zsq[row] - 2.f * t;
        float d = a + g_esq[cand];
        cv[w] = d;
        ci[w] = cand;
    }
    __syncthreads();

    if (threadIdx.x == 0) {
        float bv = cv[0]; int bi = ci[0];
#pragma unroll
        for (int r = 1; r < 4; r++) {
            float v = cv[r]; int i = ci[r];
            if (v < bv || (v == bv && i < bi)) { bv = v; bi = i; }
        }
        g_k[row] = bi;
        out[OFF_K + row] = (float)bi;
    }
}

// ---------------- z_q / neighbor gathers from refined k ----------------
__global__ __launch_bounds__(256) void gather_kernel(
    const float* __restrict__ emb, float* __restrict__ out)
{
    const int row = blockIdx.x;
    const int t = threadIdx.x;
    const int k = g_k[row];

    const int k1 = k / SOMW;
    const int k2 = k % SOMW;
    const float* src0 = emb + (size_t)k * LAT;
    const float* src1 = (k1 < SOMW - 1) ? emb + (size_t)(k + SOMW) * LAT : nullptr;
    const float* src2 = (k1 > 0)        ? emb + (size_t)(k - SOMW) * LAT : nullptr;
    const float* src4 = (k2 > 0)        ? emb + (size_t)(k - 1) * LAT    : nullptr;

    float* zq = out + OFF_ZQ + (size_t)row * LAT;
    float* nb = out + OFF_NB + (size_t)row * 5 * LAT;
    for (int i = t; i < LAT; i += 256) {
        float v0 = src0[i];
        zq[i] = v0;
        nb[i] = v0;
        nb[LAT + i]     = src1 ? src1[i] : 0.f;
        nb[2 * LAT + i] = src2 ? src2[i] : 0.f;
        nb[3 * LAT + i] = 0.f;                   // right (faithful bug: always 0)
        nb[4 * LAT + i] = src4 ? src4[i] : 0.f;
    }
}

// ---------------- x_q gather: x_q[b] = g_U[k[b]] ----------------
__global__ __launch_bounds__(256) void xq_gather_kernel(float* __restrict__ out)
{
    const int row = blockIdx.x;
    const int k = g_k[row];
    const float4* src = (const float4*)(g_U + (size_t)k * DIN);
    float4* dst = (float4*)(out + OFF_XQ + (size_t)row * DIN);
    for (int i = threadIdx.x; i < DIN / 4; i += 256)
        dst[i] = src[i];
}

// =====================================================================
extern "C" void kernel_launch(void* const* d_in, const int* in_sizes, int n_in,
                              void* d_out, int out_size)
{
    const float* x       = (const float*)d_in[0];
    const float* enc_w   = (const float*)d_in[1];
    const float* enc_b   = (const float*)d_in[2];
    const float* dec_q_w = (const float*)d_in[3];
    const float* dec_q_b = (const float*)d_in[4];
    const float* dec_e_w = (const float*)d_in[5];
    const float* dec_e_b = (const float*)d_in[6];
    const float* emb     = (const float*)d_in[7];
    float* out = (float*)d_out;

    float* zsq_p; cudaGetSymbolAddress((void**)&zsq_p, g_zsq);
    float* esq_p; cudaGetSymbolAddress((void**)&esq_p, g_esq);
    float* U_p;   cudaGetSymbolAddress((void**)&U_p,   g_U);

    dim3 blk(256);

    // 1) z_e = x @ enc_w + enc_b        [16384,2048]x[2048,512]
    gemm3t<0><<<dim3(LAT / BN, BROWS / BM), blk>>>(
        x, enc_w, enc_b, out + OFF_ZE, BROWS, LAT, DIN);

    // 2) U = emb_flat @ dec_q_w + dec_q_b   [256,512]x[512,2048]
    gemm3t<0><<<dim3(DIN / BN, KE / BM), blk>>>(
        emb, dec_q_w, dec_q_b, U_p, KE, DIN, LAT);

    // 3) row sums of squares (fp64 accumulate -> fp32)
    rowsq_kernel<<<BROWS / 8, 256>>>(out + OFF_ZE, zsq_p, BROWS, LAT);
    rowsq_kernel<<<KE / 8, 256>>>(emb, esq_p, KE, LAT);

    // 4) z_dist_flat = (zsq - 2 z_e@emb^T) + esq   [16384,512]x[256,512]^T
    gemm3t<1><<<dim3(KE / BN, BROWS / BM), blk>>>(
        out + OFF_ZE, emb, nullptr, out + OFF_DIST, BROWS, KE, LAT);

    // 5) top-4 fp32 candidates, then exact fp64 refine -> k
    argmin_top4_kernel<<<BROWS, 256>>>(out + OFF_DIST);
    refine_kernel<<<BROWS, 128>>>(out + OFF_ZE, emb, out);

    // 6) gathers from refined k
    gather_kernel<<<BROWS, 256>>>(emb, out);
    xq_gather_kernel<<<BROWS, 256>>>(out);

    // 7) x_e = z_e @ dec_e_w + dec_e_b   [16384,512]x[512,2048]
    gemm3t<0><<<dim3(DIN / BN, BROWS / BM), blk>>>(
        out + OFF_ZE, dec_e_w, dec_e_b, out + OFF_XE, BROWS, DIN, LAT);
}

// round 6
// speedup vs baseline: 1.3614x; 1.2516x over previous
#include <cuda_runtime.h>
#include <stdint.h>
#include <math_constants.h>

// ---------------- problem constants ----------------
constexpr int BROWS = 16384;
constexpr int DIN   = 2048;
constexpr int LAT   = 512;
constexpr int KE    = 256;
constexpr int SOMW  = 16;

constexpr size_t OFF_XE   = 0;
constexpr size_t OFF_XQ   = OFF_XE + (size_t)BROWS * DIN;
constexpr size_t OFF_ZE   = OFF_XQ + (size_t)BROWS * DIN;
constexpr size_t OFF_ZQ   = OFF_ZE + (size_t)BROWS * LAT;
constexpr size_t OFF_NB   = OFF_ZQ + (size_t)BROWS * LAT;
constexpr size_t OFF_K    = OFF_NB + (size_t)BROWS * 5 * LAT;
constexpr size_t OFF_DIST = OFF_K  + (size_t)BROWS;

// ---------------- device scratch ----------------
__device__ float g_zsq[BROWS];
__device__ float g_esq[KE];
__device__ float g_U[(size_t)KE * DIN];
__device__ int   g_k[BROWS];
__device__ int   g_cand[BROWS * 4];

// ---------------- helpers ----------------
__device__ __forceinline__ uint32_t smem_u32(const void* p) {
    uint32_t a;
    asm("{ .reg .u64 t; cvta.to.shared.u64 t, %1; cvt.u32.u64 %0, t; }"
        : "=r"(a) : "l"(p));
    return a;
}
__device__ __forceinline__ void cp16(uint32_t dst, const float* src) {
    asm volatile("cp.async.cg.shared.global [%0], [%1], 16;"
                 :: "r"(dst), "l"((unsigned long long)__cvta_generic_to_global(src))
                 : "memory");
}
__device__ __forceinline__ void cp_commit() {
    asm volatile("cp.async.commit_group;" ::: "memory");
}
__device__ __forceinline__ void cp_wait2() {
    asm volatile("cp.async.wait_group 2;" ::: "memory");
}
__device__ __forceinline__ void mma8(float* c, const uint32_t* a, const uint32_t* b) {
    asm volatile(
        "mma.sync.aligned.m16n8k8.row.col.f32.tf32.tf32.f32 "
        "{%0,%1,%2,%3}, {%4,%5,%6,%7}, {%8,%9}, {%0,%1,%2,%3};\n"
        : "+f"(c[0]), "+f"(c[1]), "+f"(c[2]), "+f"(c[3])
        : "r"(a[0]), "r"(a[1]), "r"(a[2]), "r"(a[3]), "r"(b[0]), "r"(b[1]));
}

// smem geometry (floats): A tile 128 rows x 32 k, stride 36 (conflict-free frags)
//                         B tile mode0: 32 k x 128 n, stride 136
//                                 mode1: 128 n x 32 k, stride 36
constexpr int ASTR  = 36;
constexpr int BSTR0 = 136;
constexpr int ABYTES = 128 * ASTR * 4;            // 18432
constexpr int BBYTES = 18432;                     // max of both modes
constexpr int STAGE  = ABYTES + BBYTES;           // 36864
constexpr int NSTAGE = 4;
constexpr int GSMEM  = STAGE * NSTAGE;            // 147456

// =====================================================================
// Pipelined tf32 mma.sync GEMM, 128x128 CTA tile, NPASS-pass fp32 emulation
// MODE 0: C = A[M,K] @ B[K,N] + bias[N]
// MODE 1: C = (g_zsq[m] - 2*(A[M,K] @ B[N,K]^T)) + g_esq[n]
// NPASS: 3 = full split (fp32-grade), 2 = split A only, 1 = raw tf32
// =====================================================================
template <int MODE, int NPASS>
__global__ __launch_bounds__(256) void gemm_mma(
    const float* __restrict__ A, const float* __restrict__ B,
    const float* __restrict__ bias, float* __restrict__ C,
    int M, int N, int K)
{
    extern __shared__ char smem[];
    const uint32_t sb = smem_u32(smem);
    const int tid = threadIdx.x, lane = tid & 31, warp = tid >> 5;
    const int wm = warp >> 1;          // 0..3 -> 32-row slice
    const int wn = warp & 1;           // 0..1 -> 64-col slice
    const int rq = lane >> 2, cq = lane & 3;
    const int m0 = blockIdx.y * 128, n0 = blockIdx.x * 128;

    // loader indices
    const int lrow = tid >> 1, lcol = (tid & 1) * 16;   // A (and B mode1)
    const int krow = tid >> 3, seg = tid & 7;           // B mode0

    float acc[2][8][4];
#pragma unroll
    for (int mt = 0; mt < 2; mt++)
#pragma unroll
        for (int nt = 0; nt < 8; nt++)
#pragma unroll
            for (int r = 0; r < 4; r++) acc[mt][nt][r] = 0.f;

    const int nch = K / 32;

    // ---- async stage issuer ----
    auto issue = [&](int c) {
        const int k0 = c * 32, buf = c & (NSTAGE - 1);
        const uint32_t ab = sb + buf * STAGE;
        const uint32_t bb = ab + ABYTES;
        const float* asrc = A + (size_t)(m0 + lrow) * K + k0 + lcol;
#pragma unroll
        for (int j = 0; j < 4; j++)
            cp16(ab + (lrow * ASTR + lcol + j * 4) * 4, asrc + j * 4);
        if (MODE == 0) {
            const float* bsrc = B + (size_t)(k0 + krow) * N + n0 + seg * 16;
#pragma unroll
            for (int j = 0; j < 4; j++)
                cp16(bb + (krow * BSTR0 + seg * 16 + j * 4) * 4, bsrc + j * 4);
        } else {
            const float* bsrc = B + (size_t)(n0 + lrow) * K + k0 + lcol;
#pragma unroll
            for (int j = 0; j < 4; j++)
                cp16(bb + (lrow * ASTR + lcol + j * 4) * 4, bsrc + j * 4);
        }
        cp_commit();
    };

    issue(0); issue(1); issue(2);

    for (int c = 0; c < nch; c++) {
        cp_wait2();
        __syncthreads();
        if (c + 3 < nch) issue(c + 3);

        const int buf = c & (NSTAGE - 1);
        const uint32_t* As = (const uint32_t*)(smem + buf * STAGE);
        const uint32_t* Bs = (const uint32_t*)(smem + buf * STAGE + ABYTES);

#pragma unroll
        for (int ks = 0; ks < 32; ks += 8) {
            // ---- raw fragments from smem ----
            uint32_t a[2][4], b[8][2];
#pragma unroll
            for (int mt = 0; mt < 2; mt++) {
                const int r0 = (wm * 32 + mt * 16 + rq) * ASTR + ks + cq;
                a[mt][0] = As[r0];
                a[mt][1] = As[r0 + 8 * ASTR];
                a[mt][2] = As[r0 + 4];
                a[mt][3] = As[r0 + 8 * ASTR + 4];
            }
#pragma unroll
            for (int nt = 0; nt < 8; nt++) {
                const int n = wn * 64 + nt * 8 + rq;
                if (MODE == 0) {
                    b[nt][0] = Bs[(ks + cq) * BSTR0 + n];
                    b[nt][1] = Bs[(ks + cq + 4) * BSTR0 + n];
                } else {
                    b[nt][0] = Bs[n * ASTR + ks + cq];
                    b[nt][1] = Bs[n * ASTR + ks + cq + 4];
                }
            }

            if (NPASS == 3) {
                uint32_t ah[2][4], al[2][4], bh[8][2], bl[8][2];
#pragma unroll
                for (int mt = 0; mt < 2; mt++)
#pragma unroll
                    for (int r = 0; r < 4; r++) {
                        ah[mt][r] = a[mt][r] & 0xFFFFE000u;
                        al[mt][r] = __float_as_uint(
                            __uint_as_float(a[mt][r]) - __uint_as_float(ah[mt][r]));
                    }
#pragma unroll
                for (int nt = 0; nt < 8; nt++)
#pragma unroll
                    for (int r = 0; r < 2; r++) {
                        bh[nt][r] = b[nt][r] & 0xFFFFE000u;
                        bl[nt][r] = __float_as_uint(
                            __uint_as_float(b[nt][r]) - __uint_as_float(bh[nt][r]));
                    }
#pragma unroll
                for (int mt = 0; mt < 2; mt++)
#pragma unroll
                    for (int nt = 0; nt < 8; nt++) {
                        mma8(acc[mt][nt], ah[mt], bl[nt]);
                        mma8(acc[mt][nt], al[mt], bh[nt]);
                        mma8(acc[mt][nt], ah[mt], bh[nt]);
                    }
            } else if (NPASS == 2) {
                uint32_t ah[2][4], al[2][4];
#pragma unroll
                for (int mt = 0; mt < 2; mt++)
#pragma unroll
                    for (int r = 0; r < 4; r++) {
                        ah[mt][r] = a[mt][r] & 0xFFFFE000u;
                        al[mt][r] = __float_as_uint(
                            __uint_as_float(a[mt][r]) - __uint_as_float(ah[mt][r]));
                    }
#pragma unroll
                for (int mt = 0; mt < 2; mt++)
#pragma unroll
                    for (int nt = 0; nt < 8; nt++) {
                        mma8(acc[mt][nt], al[mt], b[nt]);
                        mma8(acc[mt][nt], ah[mt], b[nt]);
                    }
            } else {
#pragma unroll
                for (int mt = 0; mt < 2; mt++)
#pragma unroll
                    for (int nt = 0; nt < 8; nt++)
                        mma8(acc[mt][nt], a[mt], b[nt]);
            }
        }
    }

    // ---- epilogue ----
#pragma unroll
    for (int mt = 0; mt < 2; mt++) {
        const int row = m0 + wm * 32 + mt * 16 + rq;
#pragma unroll
        for (int nt = 0; nt < 8; nt++) {
            const int col = n0 + wn * 64 + nt * 8 + 2 * cq;
            float* c = acc[mt][nt];
            if (MODE == 0) {
                const float b0 = bias[col], b1 = bias[col + 1];
                float2 v0 = make_float2(c[0] + b0, c[1] + b1);
                float2 v1 = make_float2(c[2] + b0, c[3] + b1);
                *(float2*)&C[(size_t)row * N + col] = v0;
                *(float2*)&C[(size_t)(row + 8) * N + col] = v1;
            } else {
                const float zs0 = g_zsq[row], zs1 = g_zsq[row + 8];
                const float e0 = g_esq[col], e1 = g_esq[col + 1];
                float2 v0 = make_float2((zs0 - 2.f * c[0]) + e0, (zs0 - 2.f * c[1]) + e1);
                float2 v1 = make_float2((zs1 - 2.f * c[2]) + e0, (zs1 - 2.f * c[3]) + e1);
                *(float2*)&C[(size_t)row * N + col] = v0;
                *(float2*)&C[(size_t)(row + 8) * N + col] = v1;
            }
        }
    }
}

// ---------------- per-row sum of squares, fp64 accumulate -> fp32 ----------------
__global__ void rowsq_kernel(const float* __restrict__ Z, float* __restrict__ out,
                             int rows, int cols)
{
    int row = blockIdx.x * (blockDim.x >> 5) + (threadIdx.x >> 5);
    int lane = threadIdx.x & 31;
    if (row >= rows) return;
    const float* z = Z + (size_t)row * cols;
    double s = 0.0;
    for (int j = lane; j < cols; j += 32) {
        double v = (double)z[j];
        s += v * v;
    }
#pragma unroll
    for (int o = 16; o > 0; o >>= 1) s += __shfl_xor_sync(0xffffffffu, s, o);
    if (lane == 0) out[row] = (float)s;
}

// ---------------- top-4 fp32 argmin candidates per row ----------------
__global__ __launch_bounds__(256) void argmin_top4_kernel(
    const float* __restrict__ dist)
{
    const int row = blockIdx.x;
    const int t = threadIdx.x;
    __shared__ float sv[256];
    __shared__ int   si[256];

    const float myv = dist[(size_t)row * KE + t];
    int chosen0 = -1, chosen1 = -1, chosen2 = -1;

#pragma unroll
    for (int r = 0; r < 4; r++) {
        float v = myv;
        if (t == chosen0 || t == chosen1 || t == chosen2) v = CUDART_INF_F;
        sv[t] = v;
        si[t] = t;
        __syncthreads();
#pragma unroll
        for (int s = 128; s > 0; s >>= 1) {
            if (t < s) {
                float v2 = sv[t + s]; int i2 = si[t + s];
                if (v2 < sv[t] || (v2 == sv[t] && i2 < si[t])) { sv[t] = v2; si[t] = i2; }
            }
            __syncthreads();
        }
        int w = si[0];
        if (t == 0) g_cand[row * 4 + r] = w;
        if (r == 0) chosen0 = w;
        else if (r == 1) chosen1 = w;
        else if (r == 2) chosen2 = w;
        __syncthreads();
    }
}

// ---------------- refine: exact fp64 dot for top-4 ----------------
__global__ __launch_bounds__(128) void refine_kernel(
    const float* __restrict__ ZE, const float* __restrict__ emb,
    float* __restrict__ out)
{
    const int row = blockIdx.x;
    const int w = threadIdx.x >> 5;
    const int lane = threadIdx.x & 31;

    __shared__ float cv[4];
    __shared__ int   ci[4];

    const int cand = g_cand[row * 4 + w];
    const float* z = ZE + (size_t)row * LAT;
    const float* e = emb + (size_t)cand * LAT;

    double s = 0.0;
    for (int j = lane; j < LAT; j += 32)
        s += (double)z[j] * (double)e[j];
#pragma unroll
    for (int o = 16; o > 0; o >>= 1) s += __shfl_xor_sync(0xffffffffu, s, o);

    if (lane == 0) {
        float t = (float)s;
        float a = g_zsq[row] - 2.f * t;
        float d = a + g_esq[cand];
        cv[w] = d;
        ci[w] = cand;
    }
    __syncthreads();

    if (threadIdx.x == 0) {
        float bv = cv[0]; int bi = ci[0];
#pragma unroll
        for (int r = 1; r < 4; r++) {
            float v = cv[r]; int i = ci[r];
            if (v < bv || (v == bv && i < bi)) { bv = v; bi = i; }
        }
        g_k[row] = bi;
        out[OFF_K + row] = (float)bi;
    }
}

// ---------------- z_q / neighbor gathers from refined k ----------------
__global__ __launch_bounds__(256) void gather_kernel(
    const float* __restrict__ emb, float* __restrict__ out)
{
    const int row = blockIdx.x;
    const int t = threadIdx.x;
    const int k = g_k[row];

    const int k1 = k / SOMW;
    const int k2 = k % SOMW;
    const float* src0 = emb + (size_t)k * LAT;
    const float* src1 = (k1 < SOMW - 1) ? emb + (size_t)(k + SOMW) * LAT : nullptr;
    const float* src2 = (k1 > 0)        ? emb + (size_t)(k - SOMW) * LAT : nullptr;
    const float* src4 = (k2 > 0)        ? emb + (size_t)(k - 1) * LAT    : nullptr;

    float* zq = out + OFF_ZQ + (size_t)row * LAT;
    float* nb = out + OFF_NB + (size_t)row * 5 * LAT;
    for (int i = t; i < LAT; i += 256) {
        float v0 = src0[i];
        zq[i] = v0;
        nb[i] = v0;
        nb[LAT + i]     = src1 ? src1[i] : 0.f;
        nb[2 * LAT + i] = src2 ? src2[i] : 0.f;
        nb[3 * LAT + i] = 0.f;                   // right (faithful bug: always 0)
        nb[4 * LAT + i] = src4 ? src4[i] : 0.f;
    }
}

// ---------------- x_q gather: x_q[b] = g_U[k[b]] ----------------
__global__ __launch_bounds__(256) void xq_gather_kernel(float* __restrict__ out)
{
    const int row = blockIdx.x;
    const int k = g_k[row];
    const float4* src = (const float4*)(g_U + (size_t)k * DIN);
    float4* dst = (float4*)(out + OFF_XQ + (size_t)row * DIN);
    for (int i = threadIdx.x; i < DIN / 4; i += 256)
        dst[i] = src[i];
}

// =====================================================================
extern "C" void kernel_launch(void* const* d_in, const int* in_sizes, int n_in,
                              void* d_out, int out_size)
{
    const float* x       = (const float*)d_in[0];
    const float* enc_w   = (const float*)d_in[1];
    const float* enc_b   = (const float*)d_in[2];
    const float* dec_q_w = (const float*)d_in[3];
    const float* dec_q_b = (const float*)d_in[4];
    const float* dec_e_w = (const float*)d_in[5];
    const float* dec_e_b = (const float*)d_in[6];
    const float* emb     = (const float*)d_in[7];
    float* out = (float*)d_out;

    float* zsq_p; cudaGetSymbolAddress((void**)&zsq_p, g_zsq);
    float* esq_p; cudaGetSymbolAddress((void**)&esq_p, g_esq);
    float* U_p;   cudaGetSymbolAddress((void**)&U_p,   g_U);

    cudaFuncSetAttribute(gemm_mma<0, 3>, cudaFuncAttributeMaxDynamicSharedMemorySize, GSMEM);
    cudaFuncSetAttribute(gemm_mma<0, 2>, cudaFuncAttributeMaxDynamicSharedMemorySize, GSMEM);
    cudaFuncSetAttribute(gemm_mma<1, 1>, cudaFuncAttributeMaxDynamicSharedMemorySize, GSMEM);

    dim3 blk(256);

    // 1) z_e = x @ enc_w + enc_b   (3-pass: must stay fp32-grade for argmin)
    gemm_mma<0, 3><<<dim3(LAT / 128, BROWS / 128), blk, GSMEM>>>(
        x, enc_w, enc_b, out + OFF_ZE, BROWS, LAT, DIN);

    // 2) U = emb_flat @ dec_q_w + dec_q_b   (3-pass, tiny)
    gemm_mma<0, 3><<<dim3(DIN / 128, KE / 128), blk, GSMEM>>>(
        emb, dec_q_w, dec_q_b, U_p, KE, DIN, LAT);

    // 3) row sums of squares (fp64 accumulate -> fp32)
    rowsq_kernel<<<BROWS / 8, 256>>>(out + OFF_ZE, zsq_p, BROWS, LAT);
    rowsq_kernel<<<KE / 8, 256>>>(emb, esq_p, KE, LAT);

    // 4) z_dist_flat (1-pass: output tolerance huge; argmin protected by refine)
    gemm_mma<1, 1><<<dim3(KE / 128, BROWS / 128), blk, GSMEM>>>(
        out + OFF_ZE, emb, nullptr, out + OFF_DIST, BROWS, KE, LAT);

    // 5) top-4 fp32 candidates, then exact fp64 refine -> k
    argmin_top4_kernel<<<BROWS, 256>>>(out + OFF_DIST);
    refine_kernel<<<BROWS, 128>>>(out + OFF_ZE, emb, out);

    // 6) gathers from refined k
    gather_kernel<<<BROWS, 256>>>(emb, out);
    xq_gather_kernel<<<BROWS, 256>>>(out);

    // 7) x_e = z_e @ dec_e_w + dec_e_b   (2-pass: output-only, 1.5e-4 rel)
    gemm_mma<0, 2><<<dim3(DIN / 128, BROWS / 128), blk, GSMEM>>>(
        out + OFF_ZE, dec_e_w, dec_e_b, out + OFF_XE, BROWS, DIN, LAT);
}

// round 7
// speedup vs baseline: 1.5386x; 1.1302x over previous
#include <cuda_runtime.h>
#include <stdint.h>
#include <math_constants.h>

// ---------------- problem constants ----------------
constexpr int BROWS = 16384;
constexpr int DIN   = 2048;
constexpr int LAT   = 512;
constexpr int KE    = 256;
constexpr int SOMW  = 16;

constexpr size_t OFF_XE   = 0;
constexpr size_t OFF_XQ   = OFF_XE + (size_t)BROWS * DIN;
constexpr size_t OFF_ZE   = OFF_XQ + (size_t)BROWS * DIN;
constexpr size_t OFF_ZQ   = OFF_ZE + (size_t)BROWS * LAT;
constexpr size_t OFF_NB   = OFF_ZQ + (size_t)BROWS * LAT;
constexpr size_t OFF_K    = OFF_NB + (size_t)BROWS * 5 * LAT;
constexpr size_t OFF_DIST = OFF_K  + (size_t)BROWS;

// ---------------- device scratch ----------------
__device__ float g_zsq[BROWS];
__device__ float g_esq[KE];
__device__ float g_U[(size_t)KE * DIN];
__device__ int   g_k[BROWS];
__device__ int   g_cand[BROWS * 4];

// ---------------- helpers ----------------
__device__ __forceinline__ uint32_t smem_u32(const void* p) {
    uint32_t a;
    asm("{ .reg .u64 t; cvta.to.shared.u64 t, %1; cvt.u32.u64 %0, t; }"
        : "=r"(a) : "l"(p));
    return a;
}
__device__ __forceinline__ void cp16(uint32_t dst, const float* src) {
    asm volatile("cp.async.cg.shared.global [%0], [%1], 16;"
                 :: "r"(dst), "l"((unsigned long long)__cvta_generic_to_global(src))
                 : "memory");
}
__device__ __forceinline__ void cp_commit() {
    asm volatile("cp.async.commit_group;" ::: "memory");
}
__device__ __forceinline__ void cp_wait1() {
    asm volatile("cp.async.wait_group 1;" ::: "memory");
}
__device__ __forceinline__ void mma8(float* c, const uint32_t* a, const uint32_t* b) {
    asm volatile(
        "mma.sync.aligned.m16n8k8.row.col.f32.tf32.tf32.f32 "
        "{%0,%1,%2,%3}, {%4,%5,%6,%7}, {%8,%9}, {%0,%1,%2,%3};\n"
        : "+f"(c[0]), "+f"(c[1]), "+f"(c[2]), "+f"(c[3])
        : "r"(a[0]), "r"(a[1]), "r"(a[2]), "r"(a[3]), "r"(b[0]), "r"(b[1]));
}

// smem geometry (floats)
constexpr int ASTR  = 36;
constexpr int BSTR0 = 136;
constexpr int ABYTES = 128 * ASTR * 4;            // 18432
constexpr int BBYTES = 18432;
constexpr int STAGE  = ABYTES + BBYTES;           // 36864
constexpr int NSTAGE = 3;
constexpr int GSMEM  = STAGE * NSTAGE;            // 110592

// =====================================================================
// Pipelined tf32 mma.sync GEMM, 128x128 CTA tile, 512 threads (16 warps),
// warp tile 32x32, NPASS-pass fp32 emulation.
// MODE 0: C = A[M,K] @ B[K,N] + bias[N]
// MODE 1: C = (g_zsq[m] - 2*(A[M,K] @ B[N,K]^T)) + g_esq[n]
// =====================================================================
template <int MODE, int NPASS>
__global__ __launch_bounds__(512, 1) void gemm_mma(
    const float* __restrict__ A, const float* __restrict__ B,
    const float* __restrict__ bias, float* __restrict__ C,
    int M, int N, int K)
{
    extern __shared__ char smem[];
    const uint32_t sb = smem_u32(smem);
    const int tid = threadIdx.x, lane = tid & 31, warp = tid >> 5;
    const int wm = warp >> 2;          // 0..3 -> 32-row slice
    const int wn = warp & 3;           // 0..3 -> 32-col slice
    const int rq = lane >> 2, cq = lane & 3;
    const int m0 = blockIdx.y * 128, n0 = blockIdx.x * 128;

    // loader indices (512 threads)
    const int lrow = tid >> 2, lcs = (tid & 3) * 8;     // A / B mode1: 128x32
    const int krow = tid >> 4, nseg = (tid & 15) * 8;   // B mode0: 32x128

    float acc[2][4][4];
#pragma unroll
    for (int mt = 0; mt < 2; mt++)
#pragma unroll
        for (int nt = 0; nt < 4; nt++)
#pragma unroll
            for (int r = 0; r < 4; r++) acc[mt][nt][r] = 0.f;

    const int nch = K / 32;

    auto issue = [&](int c) {
        const int k0 = c * 32, buf = c % NSTAGE;
        const uint32_t ab = sb + buf * STAGE;
        const uint32_t bb = ab + ABYTES;
        const float* asrc = A + (size_t)(m0 + lrow) * K + k0 + lcs;
        cp16(ab + (lrow * ASTR + lcs) * 4, asrc);
        cp16(ab + (lrow * ASTR + lcs + 4) * 4, asrc + 4);
        if (MODE == 0) {
            const float* bsrc = B + (size_t)(k0 + krow) * N + n0 + nseg;
            cp16(bb + (krow * BSTR0 + nseg) * 4, bsrc);
            cp16(bb + (krow * BSTR0 + nseg + 4) * 4, bsrc + 4);
        } else {
            const float* bsrc = B + (size_t)(n0 + lrow) * K + k0 + lcs;
            cp16(bb + (lrow * ASTR + lcs) * 4, bsrc);
            cp16(bb + (lrow * ASTR + lcs + 4) * 4, bsrc + 4);
        }
        cp_commit();
    };

    issue(0);
    if (nch > 1) issue(1);

    for (int c = 0; c < nch; c++) {
        cp_wait1();
        __syncthreads();
        if (c + 2 < nch) issue(c + 2);

        const int buf = c % NSTAGE;
        const uint32_t* As = (const uint32_t*)(smem + buf * STAGE);
        const uint32_t* Bs = (const uint32_t*)(smem + buf * STAGE + ABYTES);

#pragma unroll
        for (int ks = 0; ks < 32; ks += 8) {
            uint32_t a[2][4], b[4][2];
#pragma unroll
            for (int mt = 0; mt < 2; mt++) {
                const int r0 = (wm * 32 + mt * 16 + rq) * ASTR + ks + cq;
                a[mt][0] = As[r0];
                a[mt][1] = As[r0 + 8 * ASTR];
                a[mt][2] = As[r0 + 4];
                a[mt][3] = As[r0 + 8 * ASTR + 4];
            }
#pragma unroll
            for (int nt = 0; nt < 4; nt++) {
                const int n = wn * 32 + nt * 8 + rq;
                if (MODE == 0) {
                    b[nt][0] = Bs[(ks + cq) * BSTR0 + n];
                    b[nt][1] = Bs[(ks + cq + 4) * BSTR0 + n];
                } else {
                    b[nt][0] = Bs[n * ASTR + ks + cq];
                    b[nt][1] = Bs[n * ASTR + ks + cq + 4];
                }
            }

            if (NPASS == 3) {
                uint32_t ah[2][4], al[2][4], bh[4][2], bl[4][2];
#pragma unroll
                for (int mt = 0; mt < 2; mt++)
#pragma unroll
                    for (int r = 0; r < 4; r++) {
                        ah[mt][r] = a[mt][r] & 0xFFFFE000u;
                        al[mt][r] = __float_as_uint(
                            __uint_as_float(a[mt][r]) - __uint_as_float(ah[mt][r]));
                    }
#pragma unroll
                for (int nt = 0; nt < 4; nt++)
#pragma unroll
                    for (int r = 0; r < 2; r++) {
                        bh[nt][r] = b[nt][r] & 0xFFFFE000u;
                        bl[nt][r] = __float_as_uint(
                            __uint_as_float(b[nt][r]) - __uint_as_float(bh[nt][r]));
                    }
#pragma unroll
                for (int mt = 0; mt < 2; mt++)
#pragma unroll
                    for (int nt = 0; nt < 4; nt++) {
                        mma8(acc[mt][nt], ah[mt], bl[nt]);
                        mma8(acc[mt][nt], al[mt], bh[nt]);
                        mma8(acc[mt][nt], ah[mt], bh[nt]);
                    }
            } else if (NPASS == 2) {
                uint32_t ah[2][4], al[2][4];
#pragma unroll
                for (int mt = 0; mt < 2; mt++)
#pragma unroll
                    for (int r = 0; r < 4; r++) {
                        ah[mt][r] = a[mt][r] & 0xFFFFE000u;
                        al[mt][r] = __float_as_uint(
                            __uint_as_float(a[mt][r]) - __uint_as_float(ah[mt][r]));
                    }
#pragma unroll
                for (int mt = 0; mt < 2; mt++)
#pragma unroll
                    for (int nt = 0; nt < 4; nt++) {
                        mma8(acc[mt][nt], al[mt], b[nt]);
                        mma8(acc[mt][nt], ah[mt], b[nt]);
                    }
            } else {
#pragma unroll
                for (int mt = 0; mt < 2; mt++)
#pragma unroll
                    for (int nt = 0; nt < 4; nt++)
                        mma8(acc[mt][nt], a[mt], b[nt]);
            }
        }
    }

    // ---- epilogue ----
#pragma unroll
    for (int mt = 0; mt < 2; mt++) {
        const int row = m0 + wm * 32 + mt * 16 + rq;
#pragma unroll
        for (int nt = 0; nt < 4; nt++) {
            const int col = n0 + wn * 32 + nt * 8 + 2 * cq;
            float* c = acc[mt][nt];
            if (MODE == 0) {
                const float b0 = bias[col], b1 = bias[col + 1];
                float2 v0 = make_float2(c[0] + b0, c[1] + b1);
                float2 v1 = make_float2(c[2] + b0, c[3] + b1);
                *(float2*)&C[(size_t)row * N + col] = v0;
                *(float2*)&C[(size_t)(row + 8) * N + col] = v1;
            } else {
                const float zs0 = g_zsq[row], zs1 = g_zsq[row + 8];
                const float e0 = g_esq[col], e1 = g_esq[col + 1];
                float2 v0 = make_float2((zs0 - 2.f * c[0]) + e0, (zs0 - 2.f * c[1]) + e1);
                float2 v1 = make_float2((zs1 - 2.f * c[2]) + e0, (zs1 - 2.f * c[3]) + e1);
                *(float2*)&C[(size_t)row * N + col] = v0;
                *(float2*)&C[(size_t)(row + 8) * N + col] = v1;
            }
        }
    }
}

// ---------------- per-row sum of squares, fp64 accumulate -> fp32 ----------------
__global__ void rowsq_kernel(const float* __restrict__ Z, float* __restrict__ out,
                             int rows, int cols)
{
    int row = blockIdx.x * (blockDim.x >> 5) + (threadIdx.x >> 5);
    int lane = threadIdx.x & 31;
    if (row >= rows) return;
    const float* z = Z + (size_t)row * cols;
    double s = 0.0;
    for (int j = lane; j < cols; j += 32) {
        double v = (double)z[j];
        s += v * v;
    }
#pragma unroll
    for (int o = 16; o > 0; o >>= 1) s += __shfl_xor_sync(0xffffffffu, s, o);
    if (lane == 0) out[row] = (float)s;
}

// ---------------- top-4 candidates: warp per row, register scan ----------------
__global__ __launch_bounds__(256) void argmin_top4_kernel(
    const float* __restrict__ dist)
{
    const int row = blockIdx.x * 8 + (threadIdx.x >> 5);
    const int lane = threadIdx.x & 31;

    float d[8];
    const float4* src = (const float4*)(dist + (size_t)row * KE + lane * 8);
    float4 v0 = src[0], v1 = src[1];
    d[0] = v0.x; d[1] = v0.y; d[2] = v0.z; d[3] = v0.w;
    d[4] = v1.x; d[5] = v1.y; d[6] = v1.z; d[7] = v1.w;

#pragma unroll
    for (int r = 0; r < 4; r++) {
        float bv = d[0];
        int   bj = 0;
#pragma unroll
        for (int j = 1; j < 8; j++)
            if (d[j] < bv) { bv = d[j]; bj = j; }
        int bi = lane * 8 + bj;
#pragma unroll
        for (int o = 16; o > 0; o >>= 1) {
            float ov = __shfl_xor_sync(0xffffffffu, bv, o);
            int   oi = __shfl_xor_sync(0xffffffffu, bi, o);
            if (ov < bv || (ov == bv && oi < bi)) { bv = ov; bi = oi; }
        }
        if (lane == 0) g_cand[row * 4 + r] = bi;
        if ((bi >> 3) == lane) d[bi & 7] = CUDART_INF_F;
    }
}

// ---------------- refine: exact fp64 dot for top-4 ----------------
__global__ __launch_bounds__(128) void refine_kernel(
    const float* __restrict__ ZE, const float* __restrict__ emb,
    float* __restrict__ out)
{
    const int row = blockIdx.x;
    const int w = threadIdx.x >> 5;
    const int lane = threadIdx.x & 31;

    __shared__ float cv[4];
    __shared__ int   ci[4];

    const int cand = g_cand[row * 4 + w];
    const float* z = ZE + (size_t)row * LAT;
    const float* e = emb + (size_t)cand * LAT;

    double s = 0.0;
    for (int j = lane; j < LAT; j += 32)
        s += (double)z[j] * (double)e[j];
#pragma unroll
    for (int o = 16; o > 0; o >>= 1) s += __shfl_xor_sync(0xffffffffu, s, o);

    if (lane == 0) {
        float t = (float)s;
        float a = g_zsq[row] - 2.f * t;
        float d = a + g_esq[cand];
        cv[w] = d;
        ci[w] = cand;
    }
    __syncthreads();

    if (threadIdx.x == 0) {
        float bv = cv[0]; int bi = ci[0];
#pragma unroll
        for (int r = 1; r < 4; r++) {
            float v = cv[r]; int i = ci[r];
            if (v < bv || (v == bv && i < bi)) { bv = v; bi = i; }
        }
        g_k[row] = bi;
        out[OFF_K + row] = (float)bi;
    }
}

// ---------------- fused gathers: z_q, neighbors, x_q ----------------
__global__ __launch_bounds__(256) void gather_all_kernel(
    const float* __restrict__ emb, float* __restrict__ out)
{
    const int row = blockIdx.x;
    const int t = threadIdx.x;
    const int k = g_k[row];

    const int k1 = k / SOMW;
    const int k2 = k % SOMW;
    const float* src0 = emb + (size_t)k * LAT;
    const float* src1 = (k1 < SOMW - 1) ? emb + (size_t)(k + SOMW) * LAT : nullptr;
    const float* src2 = (k1 > 0)        ? emb + (size_t)(k - SOMW) * LAT : nullptr;
    const float* src4 = (k2 > 0)        ? emb + (size_t)(k - 1) * LAT    : nullptr;

    float* zq = out + OFF_ZQ + (size_t)row * LAT;
    float* nb = out + OFF_NB + (size_t)row * 5 * LAT;
#pragma unroll
    for (int i = t; i < LAT; i += 256) {
        float v0 = src0[i];
        zq[i] = v0;
        nb[i] = v0;
        nb[LAT + i]     = src1 ? src1[i] : 0.f;
        nb[2 * LAT + i] = src2 ? src2[i] : 0.f;
        nb[3 * LAT + i] = 0.f;                   // right (faithful bug: always 0)
        nb[4 * LAT + i] = src4 ? src4[i] : 0.f;
    }

    const float4* usrc = (const float4*)(g_U + (size_t)k * DIN);
    float4* dst = (float4*)(out + OFF_XQ + (size_t)row * DIN);
#pragma unroll
    for (int i = t; i < DIN / 4; i += 256)
        dst[i] = usrc[i];
}

// =====================================================================
extern "C" void kernel_launch(void* const* d_in, const int* in_sizes, int n_in,
                              void* d_out, int out_size)
{
    const float* x       = (const float*)d_in[0];
    const float* enc_w   = (const float*)d_in[1];
    const float* enc_b   = (const float*)d_in[2];
    const float* dec_q_w = (const float*)d_in[3];
    const float* dec_q_b = (const float*)d_in[4];
    const float* dec_e_w = (const float*)d_in[5];
    const float* dec_e_b = (const float*)d_in[6];
    const float* emb     = (const float*)d_in[7];
    float* out = (float*)d_out;

    float* zsq_p; cudaGetSymbolAddress((void**)&zsq_p, g_zsq);
    float* esq_p; cudaGetSymbolAddress((void**)&esq_p, g_esq);
    float* U_p;   cudaGetSymbolAddress((void**)&U_p,   g_U);

    cudaFuncSetAttribute(gemm_mma<0, 3>, cudaFuncAttributeMaxDynamicSharedMemorySize, GSMEM);
    cudaFuncSetAttribute(gemm_mma<0, 2>, cudaFuncAttributeMaxDynamicSharedMemorySize, GSMEM);
    cudaFuncSetAttribute(gemm_mma<1, 1>, cudaFuncAttributeMaxDynamicSharedMemorySize, GSMEM);

    dim3 blk(512);

    // 0) e_sq (independent of everything downstream of emb)
    rowsq_kernel<<<KE / 8, 256>>>(emb, esq_p, KE, LAT);

    // 1) U = emb_flat @ dec_q_w + dec_q_b   (3-pass, tiny)
    gemm_mma<0, 3><<<dim3(DIN / 128, KE / 128), blk, GSMEM>>>(
        emb, dec_q_w, dec_q_b, U_p, KE, DIN, LAT);

    // 2) z_e = x @ enc_w + enc_b   (3-pass: fp32-grade, bit-stable for argmin)
    gemm_mma<0, 3><<<dim3(LAT / 128, BROWS / 128), blk, GSMEM>>>(
        x, enc_w, enc_b, out + OFF_ZE, BROWS, LAT, DIN);

    // 3) z_sq
    rowsq_kernel<<<BROWS / 8, 256>>>(out + OFF_ZE, zsq_p, BROWS, LAT);

    // 4) x_e = z_e @ dec_e_w + dec_e_b   (2-pass)
    gemm_mma<0, 2><<<dim3(DIN / 128, BROWS / 128), blk, GSMEM>>>(
        out + OFF_ZE, dec_e_w, dec_e_b, out + OFF_XE, BROWS, DIN, LAT);

    // 5) z_dist_flat (1-pass; argmin protected by refine)
    gemm_mma<1, 1><<<dim3(KE / 128, BROWS / 128), blk, GSMEM>>>(
        out + OFF_ZE, emb, nullptr, out + OFF_DIST, BROWS, KE, LAT);

    // 6) top-4 candidates, fp64 refine -> k
    argmin_top4_kernel<<<BROWS / 8, 256>>>(out + OFF_DIST);
    refine_kernel<<<BROWS, 128>>>(out + OFF_ZE, emb, out);

    // 7) fused gathers (z_q, neighbors, x_q)
    gather_all_kernel<<<BROWS, 256>>>(emb, out);
}